// round 6
// baseline (speedup 1.0000x reference)
#include <cuda_runtime.h>
#include <cstdint>

#define NUM_EMBED 8192
#define ED 64
#define NTOK 32768
#define CH_STRIDE 4096
#define B_STRIDE 262144

#define OFF_LOSS 2097152
#define OFF_IDX  2097153
#define OFF_BIN  (2097153 + 32768)

#define MCTA 256                     /* tokens per CTA in pass A */
#define NCTA (NTOK / MCTA)           /* 128 */
#define NT 64                        /* codes per tile */
#define NTILES (NUM_EMBED / NT)      /* 128 */
#define CAP 32                       /* candidate slots per token */
#define TWIN 2304                    /* rigorous int window: 2*(0.5*1048*2+16)+slack */

#define ROWB 80                      /* padded smem row stride (64B int8 row) */

__device__ float g_cnorm[NUM_EMBED * ED];              // [k][c] normalized codebook fp32
__device__ float g_zn[NTOK * ED];                      // [t][c] normalized z fp32
__device__ __align__(16) unsigned char g_Bq[(size_t)NUM_EMBED * 64]; // int8 codes [k][c]
__device__ __align__(16) unsigned char g_Aq[(size_t)NTOK * 64];      // int8 z [t][c]
__device__ int g_cnt[NTOK];
__device__ __align__(4) unsigned short g_cand[(size_t)NTOK * CAP];
__device__ float g_partial[NTOK / 32];

// ===================== PTX helpers =====================
__device__ __forceinline__ uint32_t smem_u32(const void* p) {
    uint32_t a;
    asm("{ .reg .u64 t; cvta.to.shared.u64 t, %1; cvt.u32.u64 %0, t; }" : "=r"(a) : "l"(p));
    return a;
}
__device__ __forceinline__ void ldsm_x4(uint32_t* r, uint32_t addr) {
    asm volatile("ldmatrix.sync.aligned.m8n8.x4.shared.b16 {%0,%1,%2,%3}, [%4];"
        : "=r"(r[0]), "=r"(r[1]), "=r"(r[2]), "=r"(r[3]) : "r"(addr));
}
__device__ __forceinline__ void mma_s8(int* d, const uint32_t* a, uint32_t b0, uint32_t b1) {
    asm volatile("mma.sync.aligned.m16n8k32.row.col.s32.s8.s8.s32 "
        "{%0,%1,%2,%3}, {%4,%5,%6,%7}, {%8,%9}, {%0,%1,%2,%3};"
        : "+r"(d[0]), "+r"(d[1]), "+r"(d[2]), "+r"(d[3])
        : "r"(a[0]), "r"(a[1]), "r"(a[2]), "r"(a[3]), "r"(b0), "r"(b1));
}
#define CP_ASYNC16(dst, src) asm volatile("cp.async.cg.shared.global [%0], [%1], 16;" :: "r"(dst), "l"(src))
#define CP_COMMIT()          asm volatile("cp.async.commit_group;" ::: "memory")
#define CP_WAIT0()           asm volatile("cp.async.wait_group 0;" ::: "memory")
#define CP_WAIT1()           asm volatile("cp.async.wait_group 1;" ::: "memory")

__device__ __forceinline__ void pack_row(const float* x, uint32_t* w) {
#pragma unroll
    for (int j = 0; j < 16; ++j) {
        int q0 = __float2int_rn(127.f * x[4 * j + 0]);
        int q1 = __float2int_rn(127.f * x[4 * j + 1]);
        int q2 = __float2int_rn(127.f * x[4 * j + 2]);
        int q3 = __float2int_rn(127.f * x[4 * j + 3]);
        w[j] = (q0 & 0xFF) | ((q1 & 0xFF) << 8) | ((q2 & 0xFF) << 16) | ((q3 & 0xFF) << 24);
    }
}

// ===================== prep: normalize + quantize =====================
__global__ void k_prep_c(const float* __restrict__ ew) {
    int k = blockIdx.x * 128 + threadIdx.x;
    float v[64]; float ss = 0.f;
#pragma unroll
    for (int i = 0; i < 16; ++i) {
        float4 q = ((const float4*)(ew + (size_t)k * ED))[i];
        v[4*i+0] = q.x; v[4*i+1] = q.y; v[4*i+2] = q.z; v[4*i+3] = q.w;
        ss = fmaf(q.x, q.x, ss); ss = fmaf(q.y, q.y, ss);
        ss = fmaf(q.z, q.z, ss); ss = fmaf(q.w, q.w, ss);
    }
    float nm = fmaxf(__fsqrt_rn(ss), 1e-12f);
    float xn[64];
#pragma unroll
    for (int c = 0; c < 64; ++c) {
        xn[c] = __fdiv_rn(v[c], nm);
        g_cnorm[(size_t)k * ED + c] = xn[c];
    }
    uint32_t w[16];
    pack_row(xn, w);
    uint4* dst = (uint4*)(g_Bq + (size_t)k * 64);
#pragma unroll
    for (int j = 0; j < 4; ++j) dst[j] = make_uint4(w[4*j], w[4*j+1], w[4*j+2], w[4*j+3]);
}

__global__ void k_prep_z(const float* __restrict__ z) {
    int t = blockIdx.x * 128 + threadIdx.x;
    int b = t >> 12, p = t & 4095;
    const float* zb = z + (size_t)b * B_STRIDE + p;
    float v[64]; float ss = 0.f;
#pragma unroll
    for (int c = 0; c < 64; ++c) { v[c] = zb[c * CH_STRIDE]; ss = fmaf(v[c], v[c], ss); }
    float nm = fmaxf(__fsqrt_rn(ss), 1e-12f);
    float xn[64];
#pragma unroll
    for (int c = 0; c < 64; ++c) xn[c] = __fdiv_rn(v[c], nm);
    float4* zd = (float4*)(g_zn + (size_t)t * 64);
#pragma unroll
    for (int j = 0; j < 16; ++j) zd[j] = make_float4(xn[4*j], xn[4*j+1], xn[4*j+2], xn[4*j+3]);
    uint32_t w[16];
    pack_row(xn, w);
    uint4* dst = (uint4*)(g_Aq + (size_t)t * 64);
#pragma unroll
    for (int j = 0; j < 4; ++j) dst[j] = make_uint4(w[4*j], w[4*j+1], w[4*j+2], w[4*j+3]);
}

// ===================== pass A: int8 IMMA filter =====================
#define SMA 0
#define SMA_BYTES (MCTA * ROWB)              /* 20480 */
#define SMB0 SMA_BYTES
#define SMB_BYTES (NT * ROWB)                /* 5120 */
#define SMB1 (SMB0 + SMB_BYTES)
#define SMCAND (SMB1 + SMB_BYTES)            /* 30720: 256*32*2 = 16384 */
#define SMCNT (SMCAND + MCTA * CAP * 2)      /* 47104: 256*4 */
#define SMTOT (SMCNT + MCTA * 4)             /* 48128 */

__global__ __launch_bounds__(256, 1) void k_filter() {
    extern __shared__ char smem[];
    uint32_t sbase = smem_u32(smem);
    unsigned short* cand = (unsigned short*)(smem + SMCAND);
    int* cnt = (int*)(smem + SMCNT);

    const int tid = threadIdx.x, wid = tid >> 5, lane = tid & 31;
    const int tok0 = blockIdx.x * MCTA;

    for (int i = tid; i < MCTA; i += 256) cnt[i] = 0;

    // prologue: A (whole CTA) + B tile 0
    const unsigned char* Ag = g_Aq + (size_t)tok0 * 64;
    for (int i = tid; i < MCTA * 4; i += 256) {
        int row = i >> 2, c = i & 3;
        CP_ASYNC16(sbase + SMA + row * ROWB + c * 16, Ag + (size_t)row * 64 + c * 16);
    }
    for (int i = tid; i < NT * 4; i += 256) {
        int row = i >> 2, c = i & 3;
        CP_ASYNC16(sbase + SMB0 + row * ROWB + c * 16, g_Bq + (size_t)row * 64 + c * 16);
    }
    CP_COMMIT();

    // ldmatrix lane mapping (same as proven R3 kernel)
    const int lg = lane >> 3;
    const int lrow = ((lg & 1) << 3) + (lane & 7);
    const int lkc  = (lg >> 1) << 3;           // b16 units
    const int mrow0 = wid * 32;
    uint32_t aaddr0 = sbase + SMA + (uint32_t)(mrow0 + 0  + lrow) * ROWB + lkc * 2;
    uint32_t aaddr1 = sbase + SMA + (uint32_t)(mrow0 + 16 + lrow) * ROWB + lkc * 2;
    uint32_t brel0 = (uint32_t)(0  + lrow) * ROWB + lkc * 2;
    uint32_t brel1 = (uint32_t)(16 + lrow) * ROWB + lkc * 2;
    uint32_t brel2 = (uint32_t)(32 + lrow) * ROWB + lkc * 2;
    uint32_t brel3 = (uint32_t)(48 + lrow) * ROWB + lkc * 2;

    int rmax[4], rlow[4], tloc[4];
#pragma unroll
    for (int rs = 0; rs < 4; ++rs) {
        rmax[rs] = -1073741824; rlow[rs] = -1073741824;
        tloc[rs] = mrow0 + (rs >> 1) * 16 + (rs & 1) * 8 + (lane >> 2);
    }
    const int kcol0 = (lane & 3) << 1;

    for (int nt = 0; nt < NTILES; ++nt) {
        if (nt + 1 < NTILES) {
            uint32_t dstb = sbase + (((nt + 1) & 1) ? SMB1 : SMB0);
            const unsigned char* src = g_Bq + (size_t)(nt + 1) * NT * 64;
            for (int i = tid; i < NT * 4; i += 256) {
                int row = i >> 2, c = i & 3;
                CP_ASYNC16(dstb + row * ROWB + c * 16, src + (size_t)row * 64 + c * 16);
            }
            CP_COMMIT();
            CP_WAIT1();
        } else {
            CP_WAIT0();
        }
        __syncthreads();

        uint32_t bbuf = sbase + ((nt & 1) ? SMB1 : SMB0);

        int acc[2][8][4];
#pragma unroll
        for (int mf = 0; mf < 2; ++mf)
#pragma unroll
            for (int nf = 0; nf < 8; ++nf)
#pragma unroll
                for (int r = 0; r < 4; ++r) acc[mf][nf][r] = 0;

#pragma unroll
        for (int ks = 0; ks < 2; ++ks) {
            uint32_t a0[4], a1[4], bf0[4], bf1[4], bf2[4], bf3[4];
            ldsm_x4(a0, aaddr0 + ks * 32);
            ldsm_x4(a1, aaddr1 + ks * 32);
            ldsm_x4(bf0, bbuf + brel0 + ks * 32);
            ldsm_x4(bf1, bbuf + brel1 + ks * 32);
            ldsm_x4(bf2, bbuf + brel2 + ks * 32);
            ldsm_x4(bf3, bbuf + brel3 + ks * 32);
            mma_s8(acc[0][0], a0, bf0[0], bf0[2]);
            mma_s8(acc[1][0], a1, bf0[0], bf0[2]);
            mma_s8(acc[0][1], a0, bf0[1], bf0[3]);
            mma_s8(acc[1][1], a1, bf0[1], bf0[3]);
            mma_s8(acc[0][2], a0, bf1[0], bf1[2]);
            mma_s8(acc[1][2], a1, bf1[0], bf1[2]);
            mma_s8(acc[0][3], a0, bf1[1], bf1[3]);
            mma_s8(acc[1][3], a1, bf1[1], bf1[3]);
            mma_s8(acc[0][4], a0, bf2[0], bf2[2]);
            mma_s8(acc[1][4], a1, bf2[0], bf2[2]);
            mma_s8(acc[0][5], a0, bf2[1], bf2[3]);
            mma_s8(acc[1][5], a1, bf2[1], bf2[3]);
            mma_s8(acc[0][6], a0, bf3[0], bf3[2]);
            mma_s8(acc[1][6], a1, bf3[0], bf3[2]);
            mma_s8(acc[0][7], a0, bf3[1], bf3[3]);
            mma_s8(acc[1][7], a1, bf3[1], bf3[3]);
        }

        // tile max per row-slot, merged across the quad (lanes sharing tokens)
        int tmax[4];
#pragma unroll
        for (int rs = 0; rs < 4; ++rs) tmax[rs] = -1073741824;
#pragma unroll
        for (int mf = 0; mf < 2; ++mf)
#pragma unroll
            for (int h = 0; h < 2; ++h) {
                int rs = mf * 2 + h;
#pragma unroll
                for (int nf = 0; nf < 8; ++nf) {
                    tmax[rs] = max(tmax[rs], acc[mf][nf][h*2]);
                    tmax[rs] = max(tmax[rs], acc[mf][nf][h*2+1]);
                }
            }
#pragma unroll
        for (int rs = 0; rs < 4; ++rs) {
            tmax[rs] = max(tmax[rs], __shfl_xor_sync(0xffffffffu, tmax[rs], 1));
            tmax[rs] = max(tmax[rs], __shfl_xor_sync(0xffffffffu, tmax[rs], 2));
            rmax[rs] = max(rmax[rs], tmax[rs]);
            rlow[rs] = rmax[rs] - TWIN;
        }

        // push candidates within window
        int kbase = nt * NT + kcol0;
#pragma unroll
        for (int mf = 0; mf < 2; ++mf)
#pragma unroll
            for (int h = 0; h < 2; ++h) {
                int rs = mf * 2 + h;
#pragma unroll
                for (int nf = 0; nf < 8; ++nf) {
                    int kk = kbase + nf * 8;
                    int v0 = acc[mf][nf][h*2], v1 = acc[mf][nf][h*2+1];
                    if (v0 >= rlow[rs]) {
                        int pos = atomicAdd(&cnt[tloc[rs]], 1);
                        if (pos < CAP) cand[tloc[rs] * CAP + pos] = (unsigned short)kk;
                    }
                    if (v1 >= rlow[rs]) {
                        int pos = atomicAdd(&cnt[tloc[rs]], 1);
                        if (pos < CAP) cand[tloc[rs] * CAP + pos] = (unsigned short)(kk + 1);
                    }
                }
            }
        __syncthreads();
    }

    for (int i = tid; i < MCTA; i += 256) g_cnt[tok0 + i] = cnt[i];
    uint32_t* cg = (uint32_t*)g_cand + (size_t)tok0 * CAP / 2;
    const uint32_t* cs = (const uint32_t*)cand;
    for (int i = tid; i < MCTA * CAP / 2; i += 256) cg[i] = cs[i];
}

// ===================== resolve + epilogue =====================
__global__ __launch_bounds__(128, 4) void k_resolve(const float* __restrict__ z,
                                                    const float* __restrict__ ew,
                                                    float* __restrict__ out_zq,
                                                    float* __restrict__ out_idx,
                                                    float* __restrict__ out_bin) {
    __shared__ float zs[32 * 65];
    __shared__ float zr[64 * 32];
    __shared__ float bvq[128];
    __shared__ int   biq[128];
    __shared__ int   idxs[32];
    __shared__ float red[128];

    const int tid = threadIdx.x, warp = tid >> 5, lane = tid & 31;
    const int tok0 = blockIdx.x * 32;
    const int b = tok0 >> 12, p0 = tok0 & 4095;
    const float* zb = z + (size_t)b * B_STRIDE + p0;

    for (int i = tid; i < 2048; i += 128) {
        int tk = i >> 6, c = i & 63;
        zs[tk * 65 + c] = g_zn[(size_t)(tok0 + tk) * 64 + c];
    }
    for (int i = tid; i < 512; i += 128) {
        int c = i >> 3, q = i & 7;
        float4 v = ((const float4*)(zb + c * CH_STRIDE))[q];
        ((float4*)(zr + c * 32))[q] = v;
    }
    __syncthreads();

    // candidate resolution: 4 threads per token
    {
        int tk = tid >> 2, q = tid & 3;
        int gtok = tok0 + tk;
        int n = g_cnt[gtok];
        float bv = -1e30f; int bi = 0x7FFFFFFF;
        if (n <= CAP) {
            const float* za = zs + tk * 65;
            for (int j = q; j < n; j += 4) {
                int k = g_cand[(size_t)gtok * CAP + j];
                const float* cr = g_cnorm + (size_t)k * ED;
                float d = 0.f;
#pragma unroll 16
                for (int c = 0; c < 64; ++c) d = fmaf(za[c], cr[c], d);
                if (d > bv || (d == bv && k < bi)) { bv = d; bi = k; }
            }
        }
        bvq[tid] = bv; biq[tid] = bi;
    }
    __syncthreads();
    if (tid < 32) {
        float v = bvq[tid * 4]; int i = biq[tid * 4];
#pragma unroll
        for (int q = 1; q < 4; ++q) {
            float v2 = bvq[tid * 4 + q]; int i2 = biq[tid * 4 + q];
            if (v2 > v || (v2 == v && i2 < i)) { v = v2; i = i2; }
        }
        idxs[tid] = i;
    }
    __syncthreads();

    // overflow tokens: full exact scan (rare)
    for (int tk = 0; tk < 32; ++tk) {
        if (g_cnt[tok0 + tk] > CAP) {
            const float* za = zs + tk * 65;
            float bv = -1e30f; int bi = 0x7FFFFFFF;
            for (int k = tid; k < NUM_EMBED; k += 128) {
                const float* cr = g_cnorm + (size_t)k * ED;
                float d = 0.f;
#pragma unroll 16
                for (int c = 0; c < 64; ++c) d = fmaf(za[c], cr[c], d);
                if (d > bv || (d == bv && k < bi)) { bv = d; bi = k; }
            }
            bvq[tid] = bv; biq[tid] = bi;
            __syncthreads();
            for (int s = 64; s > 0; s >>= 1) {
                if (tid < s) {
                    float v2 = bvq[tid + s]; int i2 = biq[tid + s];
                    if (v2 > bvq[tid] || (v2 == bvq[tid] && i2 < biq[tid])) {
                        bvq[tid] = v2; biq[tid] = i2;
                    }
                }
                __syncthreads();
            }
            if (tid == 0) idxs[tk] = biq[0];
            __syncthreads();
        }
    }

    // fused epilogue: gather, STE output, loss partial, idx, bincount
    int myidx = idxs[lane];
    const float4* er = (const float4*)(ew + (size_t)myidx * ED + warp * 16);
    float4 e0 = er[0], e1 = er[1], e2 = er[2], e3 = er[3];
    float vals[16] = {e0.x, e0.y, e0.z, e0.w, e1.x, e1.y, e1.z, e1.w,
                      e2.x, e2.y, e2.z, e2.w, e3.x, e3.y, e3.z, e3.w};
    float ssq = 0.f;
#pragma unroll
    for (int j = 0; j < 16; ++j) {
        int ch = warp * 16 + j;
        float zc = zr[ch * 32 + lane];
        float d  = vals[j] - zc;
        out_zq[(size_t)(b * 64 + ch) * 4096 + p0 + lane] = zc + d;
        ssq = fmaf(d, d, ssq);
    }
    red[tid] = ssq;
    __syncthreads();
    for (int s = 64; s > 0; s >>= 1) {
        if (tid < s) red[tid] += red[tid + s];
        __syncthreads();
    }
    if (tid == 0) g_partial[blockIdx.x] = red[0];

    if (tid < 32) {
        out_idx[tok0 + tid] = (float)idxs[tid];
        atomicAdd(&out_bin[idxs[tid]], 1.0f);
    }
}

// ---------------- loss finalize ----------------
__global__ void k4_loss(float* __restrict__ out_loss) {
    int lane = threadIdx.x;
    float s = 0.f;
    for (int i = lane * 32; i < lane * 32 + 32; ++i) s += g_partial[i];
#pragma unroll
    for (int off = 16; off > 0; off >>= 1)
        s += __shfl_xor_sync(0xffffffffu, s, off);
    if (lane == 0) {
        float m = s / 2097152.0f;
        out_loss[0] = 0.25f * m + m;
    }
}

extern "C" void kernel_launch(void* const* d_in, const int* in_sizes, int n_in,
                              void* d_out, int out_size) {
    const float* z  = (const float*)d_in[0];
    const float* ew = (const float*)d_in[1];
    float* out      = (float*)d_out;

    float* out_zq   = out;
    float* out_loss = out + OFF_LOSS;
    float* out_idx  = out + OFF_IDX;
    float* out_bin  = out + OFF_BIN;

    cudaMemsetAsync(out_bin, 0, NUM_EMBED * sizeof(float));

    k_prep_c<<<NUM_EMBED / 128, 128>>>(ew);
    k_prep_z<<<NTOK / 128, 128>>>(z);

    cudaFuncSetAttribute(k_filter, cudaFuncAttributeMaxDynamicSharedMemorySize, SMTOT);
    k_filter<<<NCTA, 256, SMTOT>>>();

    k_resolve<<<NTOK / 32, 128>>>(z, ew, out_zq, out_idx, out_bin);

    k4_loss<<<1, 32>>>(out_loss);
}

// round 7
// speedup vs baseline: 16.2337x; 16.2337x over previous
#include <cuda_runtime.h>
#include <cstdint>

#define NUM_EMBED 8192
#define ED 64
#define NTOK 32768
#define CH_STRIDE 4096
#define B_STRIDE 262144

#define OFF_LOSS 2097152
#define OFF_IDX  2097153
#define OFF_BIN  (2097153 + 32768)

#define MCTA 128                     /* tokens per CTA in filter */
#define NCTA (NTOK / MCTA)           /* 256 */
#define NT 64                        /* codes per tile */
#define NTILES (NUM_EMBED / NT)      /* 128 */
#define CAP 48                       /* candidate slots per token */

#define ROWB 80                      /* padded smem row stride */

__device__ float g_cnorm[NUM_EMBED * ED];              // [k][c] normalized codebook fp32
__device__ float g_zn[NTOK * ED];                      // [t][c] normalized z fp32
__device__ __align__(16) unsigned char g_Bq[(size_t)NUM_EMBED * 64]; // int8 codes
__device__ __align__(16) unsigned char g_Aq[(size_t)NTOK * 64];      // int8 z
__device__ int g_ea_i[NTOK];                           // per-token int error bound
__device__ int g_ebmax_i;                              // max per-code int error bound
__device__ int g_cnt[NTOK];
__device__ __align__(4) unsigned short g_cand[(size_t)NTOK * CAP];
__device__ float g_partial[NTOK / 32];

// ===================== PTX helpers =====================
__device__ __forceinline__ uint32_t smem_u32(const void* p) {
    uint32_t a;
    asm("{ .reg .u64 t; cvta.to.shared.u64 t, %1; cvt.u32.u64 %0, t; }" : "=r"(a) : "l"(p));
    return a;
}
__device__ __forceinline__ void ldsm_x4(uint32_t* r, uint32_t addr) {
    asm volatile("ldmatrix.sync.aligned.m8n8.x4.shared.b16 {%0,%1,%2,%3}, [%4];"
        : "=r"(r[0]), "=r"(r[1]), "=r"(r[2]), "=r"(r[3]) : "r"(addr));
}
__device__ __forceinline__ void mma_s8(int* d, const uint32_t* a, uint32_t b0, uint32_t b1) {
    asm volatile("mma.sync.aligned.m16n8k32.row.col.s32.s8.s8.s32 "
        "{%0,%1,%2,%3}, {%4,%5,%6,%7}, {%8,%9}, {%0,%1,%2,%3};"
        : "+r"(d[0]), "+r"(d[1]), "+r"(d[2]), "+r"(d[3])
        : "r"(a[0]), "r"(a[1]), "r"(a[2]), "r"(a[3]), "r"(b0), "r"(b1));
}
#define CP_ASYNC16(dst, src) asm volatile("cp.async.cg.shared.global [%0], [%1], 16;" :: "r"(dst), "l"(src))
#define CP_COMMIT()          asm volatile("cp.async.commit_group;" ::: "memory")
#define CP_WAIT0()           asm volatile("cp.async.wait_group 0;" ::: "memory")
#define CP_WAIT1()           asm volatile("cp.async.wait_group 1;" ::: "memory")

// quantize + exact residual norm; returns int error bound (127^2 units)
__device__ __forceinline__ int pack_row_err(const float* x, uint32_t* w) {
    float es = 0.f;
#pragma unroll
    for (int j = 0; j < 16; ++j) {
        int q[4];
#pragma unroll
        for (int u = 0; u < 4; ++u) {
            float xv = x[4 * j + u];
            q[u] = __float2int_rn(127.f * xv);
            float e = xv - (float)q[u] * (1.f / 127.f);
            es = fmaf(e, e, es);
        }
        w[j] = (q[0] & 0xFF) | ((q[1] & 0xFF) << 8) | ((q[2] & 0xFF) << 16) | ((q[3] & 0xFF) << 24);
    }
    float en = __fsqrt_rn(es) * 1.02f + 1e-4f;   // margin for fp rounding
    return (int)(16129.f * en) + 16;
}

// ===================== init =====================
__global__ void k0_init() { g_ebmax_i = 0; }

// ===================== prep =====================
__global__ void k_prep_c(const float* __restrict__ ew) {
    int k = blockIdx.x * 128 + threadIdx.x;
    float v[64]; float ss = 0.f;
#pragma unroll
    for (int i = 0; i < 16; ++i) {
        float4 q = ((const float4*)(ew + (size_t)k * ED))[i];
        v[4*i+0] = q.x; v[4*i+1] = q.y; v[4*i+2] = q.z; v[4*i+3] = q.w;
        ss = fmaf(q.x, q.x, ss); ss = fmaf(q.y, q.y, ss);
        ss = fmaf(q.z, q.z, ss); ss = fmaf(q.w, q.w, ss);
    }
    float nm = fmaxf(__fsqrt_rn(ss), 1e-12f);
    float xn[64];
#pragma unroll
    for (int c = 0; c < 64; ++c) {
        xn[c] = __fdiv_rn(v[c], nm);
        g_cnorm[(size_t)k * ED + c] = xn[c];
    }
    uint32_t w[16];
    int eb = pack_row_err(xn, w);
    atomicMax(&g_ebmax_i, eb);
    uint4* dst = (uint4*)(g_Bq + (size_t)k * 64);
#pragma unroll
    for (int j = 0; j < 4; ++j) dst[j] = make_uint4(w[4*j], w[4*j+1], w[4*j+2], w[4*j+3]);
}

__global__ void k_prep_z(const float* __restrict__ z) {
    int t = blockIdx.x * 128 + threadIdx.x;
    int b = t >> 12, p = t & 4095;
    const float* zb = z + (size_t)b * B_STRIDE + p;
    float v[64]; float ss = 0.f;
#pragma unroll
    for (int c = 0; c < 64; ++c) { v[c] = zb[c * CH_STRIDE]; ss = fmaf(v[c], v[c], ss); }
    float nm = fmaxf(__fsqrt_rn(ss), 1e-12f);
    float xn[64];
#pragma unroll
    for (int c = 0; c < 64; ++c) xn[c] = __fdiv_rn(v[c], nm);
    float4* zd = (float4*)(g_zn + (size_t)t * 64);
#pragma unroll
    for (int j = 0; j < 16; ++j) zd[j] = make_float4(xn[4*j], xn[4*j+1], xn[4*j+2], xn[4*j+3]);
    uint32_t w[16];
    g_ea_i[t] = pack_row_err(xn, w);
    uint4* dst = (uint4*)(g_Aq + (size_t)t * 64);
#pragma unroll
    for (int j = 0; j < 4; ++j) dst[j] = make_uint4(w[4*j], w[4*j+1], w[4*j+2], w[4*j+3]);
}

// ===================== pass A: two-phase IMMA filter =====================
#define SMA 0
#define SMA_BYTES (MCTA * ROWB)              /* 10240 */
#define SMB0 SMA_BYTES
#define SMB_BYTES (NT * ROWB)                /* 5120 */
#define SMB1 (SMB0 + SMB_BYTES)
#define SMRMAX (SMB1 + SMB_BYTES)            /* 20480: 128*4 */
#define SMCNT (SMRMAX + MCTA * 4)            /* 20992: 128*4 */
#define SMCAND (SMCNT + MCTA * 4)            /* 21504: 128*48*2 = 12288 */
#define SMTOT (SMCAND + MCTA * CAP * 2)      /* 33792 */

__global__ __launch_bounds__(256, 2) void k_filter() {
    extern __shared__ char smem[];
    uint32_t sbase = smem_u32(smem);
    int* rmaxs = (int*)(smem + SMRMAX);
    int* cnt = (int*)(smem + SMCNT);
    unsigned short* cand = (unsigned short*)(smem + SMCAND);

    const int tid = threadIdx.x, wid = tid >> 5, lane = tid & 31;
    const int tok0 = blockIdx.x * MCTA;

    for (int i = tid; i < MCTA; i += 256) cnt[i] = 0;

    // A prologue (128 rows x 64B)
    const unsigned char* Ag = g_Aq + (size_t)tok0 * 64;
    for (int i = tid; i < MCTA * 4; i += 256) {
        int row = i >> 2, c = i & 3;
        CP_ASYNC16(sbase + SMA + row * ROWB + c * 16, Ag + (size_t)row * 64 + c * 16);
    }
    for (int i = tid; i < NT * 4; i += 256) {
        int row = i >> 2, c = i & 3;
        CP_ASYNC16(sbase + SMB0 + row * ROWB + c * 16, g_Bq + (size_t)row * 64 + c * 16);
    }
    CP_COMMIT();

    // ldmatrix lane mapping (proven in R6)
    const int lg = lane >> 3;
    const int lrow = ((lg & 1) << 3) + (lane & 7);
    const int lkc  = (lg >> 1) << 3;
    const int mrow0 = wid * 16;
    const uint32_t aaddr = sbase + SMA + (uint32_t)(mrow0 + lrow) * ROWB + lkc * 2;
    const uint32_t brel0 = (uint32_t)(0  + lrow) * ROWB + lkc * 2;
    const uint32_t brel1 = (uint32_t)(16 + lrow) * ROWB + lkc * 2;
    const uint32_t brel2 = (uint32_t)(32 + lrow) * ROWB + lkc * 2;
    const uint32_t brel3 = (uint32_t)(48 + lrow) * ROWB + lkc * 2;
    const int kcol0 = (lane & 3) << 1;
    const int row0 = mrow0 + (lane >> 2);

    int rmax0 = -1073741824, rmax1 = -1073741824;

    // ---------------- phase 1: max only ----------------
    for (int nt = 0; nt < NTILES; ++nt) {
        if (nt + 1 < NTILES) {
            uint32_t dstb = sbase + (((nt + 1) & 1) ? SMB1 : SMB0);
            const unsigned char* src = g_Bq + (size_t)(nt + 1) * NT * 64;
            for (int i = tid; i < NT * 4; i += 256) {
                int row = i >> 2, c = i & 3;
                CP_ASYNC16(dstb + row * ROWB + c * 16, src + (size_t)row * 64 + c * 16);
            }
            CP_COMMIT();
            CP_WAIT1();
        } else {
            CP_WAIT0();
        }
        __syncthreads();

        uint32_t bbuf = sbase + ((nt & 1) ? SMB1 : SMB0);
        int acc[8][4];
#pragma unroll
        for (int nf = 0; nf < 8; ++nf)
#pragma unroll
            for (int r = 0; r < 4; ++r) acc[nf][r] = 0;

#pragma unroll
        for (int ks = 0; ks < 2; ++ks) {
            uint32_t a0[4], bf0[4], bf1[4], bf2[4], bf3[4];
            ldsm_x4(a0, aaddr + ks * 32);
            ldsm_x4(bf0, bbuf + brel0 + ks * 32);
            ldsm_x4(bf1, bbuf + brel1 + ks * 32);
            ldsm_x4(bf2, bbuf + brel2 + ks * 32);
            ldsm_x4(bf3, bbuf + brel3 + ks * 32);
            mma_s8(acc[0], a0, bf0[0], bf0[2]);
            mma_s8(acc[1], a0, bf0[1], bf0[3]);
            mma_s8(acc[2], a0, bf1[0], bf1[2]);
            mma_s8(acc[3], a0, bf1[1], bf1[3]);
            mma_s8(acc[4], a0, bf2[0], bf2[2]);
            mma_s8(acc[5], a0, bf2[1], bf2[3]);
            mma_s8(acc[6], a0, bf3[0], bf3[2]);
            mma_s8(acc[7], a0, bf3[1], bf3[3]);
        }
#pragma unroll
        for (int nf = 0; nf < 8; ++nf) {
            rmax0 = max(rmax0, max(acc[nf][0], acc[nf][1]));
            rmax1 = max(rmax1, max(acc[nf][2], acc[nf][3]));
        }
        __syncthreads();
    }

    // quad merge, publish per-row max
    rmax0 = max(rmax0, __shfl_xor_sync(0xffffffffu, rmax0, 1));
    rmax0 = max(rmax0, __shfl_xor_sync(0xffffffffu, rmax0, 2));
    rmax1 = max(rmax1, __shfl_xor_sync(0xffffffffu, rmax1, 1));
    rmax1 = max(rmax1, __shfl_xor_sync(0xffffffffu, rmax1, 2));
    if ((lane & 3) == 0) {
        rmaxs[row0] = rmax0;
        rmaxs[row0 + 8] = rmax1;
    }
    __syncthreads();

    const int ebm = g_ebmax_i;
    const int thr0 = rmaxs[row0]     - (2 * (g_ea_i[tok0 + row0]     + ebm) + 64);
    const int thr1 = rmaxs[row0 + 8] - (2 * (g_ea_i[tok0 + row0 + 8] + ebm) + 64);

    // ---------------- phase 2: push candidates ----------------
    for (int i = tid; i < NT * 4; i += 256) {
        int row = i >> 2, c = i & 3;
        CP_ASYNC16(sbase + SMB0 + row * ROWB + c * 16, g_Bq + (size_t)row * 64 + c * 16);
    }
    CP_COMMIT();

    for (int nt = 0; nt < NTILES; ++nt) {
        if (nt + 1 < NTILES) {
            uint32_t dstb = sbase + (((nt + 1) & 1) ? SMB1 : SMB0);
            const unsigned char* src = g_Bq + (size_t)(nt + 1) * NT * 64;
            for (int i = tid; i < NT * 4; i += 256) {
                int row = i >> 2, c = i & 3;
                CP_ASYNC16(dstb + row * ROWB + c * 16, src + (size_t)row * 64 + c * 16);
            }
            CP_COMMIT();
            CP_WAIT1();
        } else {
            CP_WAIT0();
        }
        __syncthreads();

        uint32_t bbuf = sbase + ((nt & 1) ? SMB1 : SMB0);
        int acc[8][4];
#pragma unroll
        for (int nf = 0; nf < 8; ++nf)
#pragma unroll
            for (int r = 0; r < 4; ++r) acc[nf][r] = 0;

#pragma unroll
        for (int ks = 0; ks < 2; ++ks) {
            uint32_t a0[4], bf0[4], bf1[4], bf2[4], bf3[4];
            ldsm_x4(a0, aaddr + ks * 32);
            ldsm_x4(bf0, bbuf + brel0 + ks * 32);
            ldsm_x4(bf1, bbuf + brel1 + ks * 32);
            ldsm_x4(bf2, bbuf + brel2 + ks * 32);
            ldsm_x4(bf3, bbuf + brel3 + ks * 32);
            mma_s8(acc[0], a0, bf0[0], bf0[2]);
            mma_s8(acc[1], a0, bf0[1], bf0[3]);
            mma_s8(acc[2], a0, bf1[0], bf1[2]);
            mma_s8(acc[3], a0, bf1[1], bf1[3]);
            mma_s8(acc[4], a0, bf2[0], bf2[2]);
            mma_s8(acc[5], a0, bf2[1], bf2[3]);
            mma_s8(acc[6], a0, bf3[0], bf3[2]);
            mma_s8(acc[7], a0, bf3[1], bf3[3]);
        }

        int kbase = nt * NT + kcol0;
#pragma unroll
        for (int nf = 0; nf < 8; ++nf) {
            int kk = kbase + nf * 8;
            if (acc[nf][0] >= thr0) {
                int pos = atomicAdd(&cnt[row0], 1);
                if (pos < CAP) cand[row0 * CAP + pos] = (unsigned short)kk;
            }
            if (acc[nf][1] >= thr0) {
                int pos = atomicAdd(&cnt[row0], 1);
                if (pos < CAP) cand[row0 * CAP + pos] = (unsigned short)(kk + 1);
            }
            if (acc[nf][2] >= thr1) {
                int pos = atomicAdd(&cnt[row0 + 8], 1);
                if (pos < CAP) cand[(row0 + 8) * CAP + pos] = (unsigned short)kk;
            }
            if (acc[nf][3] >= thr1) {
                int pos = atomicAdd(&cnt[row0 + 8], 1);
                if (pos < CAP) cand[(row0 + 8) * CAP + pos] = (unsigned short)(kk + 1);
            }
        }
        __syncthreads();
    }

    for (int i = tid; i < MCTA; i += 256) g_cnt[tok0 + i] = cnt[i];
    uint32_t* cg = (uint32_t*)g_cand + (size_t)tok0 * CAP / 2;
    const uint32_t* cs = (const uint32_t*)cand;
    for (int i = tid; i < MCTA * CAP / 2; i += 256) cg[i] = cs[i];
}

// ===================== resolve + epilogue (proven in R6) =====================
__global__ __launch_bounds__(128, 4) void k_resolve(const float* __restrict__ z,
                                                    const float* __restrict__ ew,
                                                    float* __restrict__ out_zq,
                                                    float* __restrict__ out_idx,
                                                    float* __restrict__ out_bin) {
    __shared__ float zs[32 * 65];
    __shared__ float zr[64 * 32];
    __shared__ float bvq[128];
    __shared__ int   biq[128];
    __shared__ int   idxs[32];
    __shared__ float red[128];

    const int tid = threadIdx.x, warp = tid >> 5, lane = tid & 31;
    const int tok0 = blockIdx.x * 32;
    const int b = tok0 >> 12, p0 = tok0 & 4095;
    const float* zb = z + (size_t)b * B_STRIDE + p0;

    for (int i = tid; i < 2048; i += 128) {
        int tk = i >> 6, c = i & 63;
        zs[tk * 65 + c] = g_zn[(size_t)(tok0 + tk) * 64 + c];
    }
    for (int i = tid; i < 512; i += 128) {
        int c = i >> 3, q = i & 7;
        float4 v = ((const float4*)(zb + c * CH_STRIDE))[q];
        ((float4*)(zr + c * 32))[q] = v;
    }
    __syncthreads();

    {
        int tk = tid >> 2, q = tid & 3;
        int gtok = tok0 + tk;
        int n = g_cnt[gtok];
        float bv = -1e30f; int bi = 0x7FFFFFFF;
        if (n <= CAP) {
            const float* za = zs + tk * 65;
            for (int j = q; j < n; j += 4) {
                int k = g_cand[(size_t)gtok * CAP + j];
                const float* cr = g_cnorm + (size_t)k * ED;
                float d = 0.f;
#pragma unroll 16
                for (int c = 0; c < 64; ++c) d = fmaf(za[c], cr[c], d);
                if (d > bv || (d == bv && k < bi)) { bv = d; bi = k; }
            }
        }
        bvq[tid] = bv; biq[tid] = bi;
    }
    __syncthreads();
    if (tid < 32) {
        float v = bvq[tid * 4]; int i = biq[tid * 4];
#pragma unroll
        for (int q = 1; q < 4; ++q) {
            float v2 = bvq[tid * 4 + q]; int i2 = biq[tid * 4 + q];
            if (v2 > v || (v2 == v && i2 < i)) { v = v2; i = i2; }
        }
        idxs[tid] = i;
    }
    __syncthreads();

    // overflow tokens: full exact scan (rare)
    for (int tk = 0; tk < 32; ++tk) {
        if (g_cnt[tok0 + tk] > CAP) {
            const float* za = zs + tk * 65;
            float bv = -1e30f; int bi = 0x7FFFFFFF;
            for (int k = tid; k < NUM_EMBED; k += 128) {
                const float* cr = g_cnorm + (size_t)k * ED;
                float d = 0.f;
#pragma unroll 16
                for (int c = 0; c < 64; ++c) d = fmaf(za[c], cr[c], d);
                if (d > bv || (d == bv && k < bi)) { bv = d; bi = k; }
            }
            bvq[tid] = bv; biq[tid] = bi;
            __syncthreads();
            for (int s = 64; s > 0; s >>= 1) {
                if (tid < s) {
                    float v2 = bvq[tid + s]; int i2 = biq[tid + s];
                    if (v2 > bvq[tid] || (v2 == bvq[tid] && i2 < biq[tid])) {
                        bvq[tid] = v2; biq[tid] = i2;
                    }
                }
                __syncthreads();
            }
            if (tid == 0) idxs[tk] = biq[0];
            __syncthreads();
        }
    }

    int myidx = idxs[lane];
    const float4* er = (const float4*)(ew + (size_t)myidx * ED + warp * 16);
    float4 e0 = er[0], e1 = er[1], e2 = er[2], e3 = er[3];
    float vals[16] = {e0.x, e0.y, e0.z, e0.w, e1.x, e1.y, e1.z, e1.w,
                      e2.x, e2.y, e2.z, e2.w, e3.x, e3.y, e3.z, e3.w};
    float ssq = 0.f;
#pragma unroll
    for (int j = 0; j < 16; ++j) {
        int ch = warp * 16 + j;
        float zc = zr[ch * 32 + lane];
        float d  = vals[j] - zc;
        out_zq[(size_t)(b * 64 + ch) * 4096 + p0 + lane] = zc + d;
        ssq = fmaf(d, d, ssq);
    }
    red[tid] = ssq;
    __syncthreads();
    for (int s = 64; s > 0; s >>= 1) {
        if (tid < s) red[tid] += red[tid + s];
        __syncthreads();
    }
    if (tid == 0) g_partial[blockIdx.x] = red[0];

    if (tid < 32) {
        out_idx[tok0 + tid] = (float)idxs[tid];
        atomicAdd(&out_bin[idxs[tid]], 1.0f);
    }
}

// ---------------- loss finalize ----------------
__global__ void k4_loss(float* __restrict__ out_loss) {
    int lane = threadIdx.x;
    float s = 0.f;
    for (int i = lane * 32; i < lane * 32 + 32; ++i) s += g_partial[i];
#pragma unroll
    for (int off = 16; off > 0; off >>= 1)
        s += __shfl_xor_sync(0xffffffffu, s, off);
    if (lane == 0) {
        float m = s / 2097152.0f;
        out_loss[0] = 0.25f * m + m;
    }
}

extern "C" void kernel_launch(void* const* d_in, const int* in_sizes, int n_in,
                              void* d_out, int out_size) {
    const float* z  = (const float*)d_in[0];
    const float* ew = (const float*)d_in[1];
    float* out      = (float*)d_out;

    float* out_zq   = out;
    float* out_loss = out + OFF_LOSS;
    float* out_idx  = out + OFF_IDX;
    float* out_bin  = out + OFF_BIN;

    cudaMemsetAsync(out_bin, 0, NUM_EMBED * sizeof(float));

    k0_init<<<1, 1>>>();
    k_prep_c<<<NUM_EMBED / 128, 128>>>(ew);
    k_prep_z<<<NTOK / 128, 128>>>(z);

    cudaFuncSetAttribute(k_filter, cudaFuncAttributeMaxDynamicSharedMemorySize, SMTOT);
    k_filter<<<NCTA, 256, SMTOT>>>();

    k_resolve<<<NTOK / 32, 128>>>(z, ew, out_zq, out_idx, out_bin);

    k4_loss<<<1, 32>>>(out_loss);
}